// round 2
// baseline (speedup 1.0000x reference)
#include <cuda_runtime.h>

// TSK fuzzy system: out[n] = sum_r fg_bar[n,r] * (x[n]·W[r] + b[r])
// fg_bar separable-normalized: mg_norm[n,m,j] = mg/sum_j mg,
// fg_bar[n,r] = prod_m mg_norm[n,m,digit_m(r)], digits MSB-first (j0 most significant).
// out[n] = x[n]·A[n] + c[n],  A[n] = sum_r fg_bar W[r],  c[n] = sum_r fg_bar b[r].

#define NSAMP 1024
#define MDIM 8
#define NMF4 4
#define RRULES 65536
#define GY 32      // rule-chunk groups (grid.y); each CTA covers 8 chunks of 256 rules
#define STILES 32  // sample tiles of 32 (grid.x)

__device__ float g_mg[NSAMP * 32];            // normalized memberships [n][m][j]
__device__ float g_part[GY * NSAMP * 12];     // partials [gy][n][12] (9 used: A0..A7, c)

// ---------------- kernel 1: normalized memberships ----------------
__global__ void mg_kernel(const float* __restrict__ x,
                          const float* __restrict__ center,
                          const float* __restrict__ sigma) {
    int n = blockIdx.x * blockDim.x + threadIdx.x;
    if (n >= NSAMP) return;
#pragma unroll
    for (int m = 0; m < MDIM; m++) {
        float xv = x[n * MDIM + m];
        float e[NMF4];
        float s = 0.f;
#pragma unroll
        for (int j = 0; j < NMF4; j++) {
            float d = xv - center[m * NMF4 + j];
            float sg = sigma[m * NMF4 + j];
            e[j] = expf(-d * d * 0.5f * sg * sg);
            s += e[j];
        }
        float inv = 1.0f / s;
#pragma unroll
        for (int j = 0; j < NMF4; j++)
            g_mg[n * 32 + m * 4 + j] = e[j] * inv;
    }
}

// ---------------- packed f32x2 helpers (Blackwell) ----------------
__device__ __forceinline__ unsigned long long pack2(float f) {
    unsigned long long r;
    asm("mov.b64 %0, {%1, %1};" : "=l"(r) : "f"(f));
    return r;
}
__device__ __forceinline__ void fma2(unsigned long long& d,
                                     unsigned long long a,
                                     unsigned long long b) {
    asm("fma.rn.f32x2 %0, %1, %2, %0;" : "+l"(d) : "l"(a), "l"(b));
}

// ---------------- kernel 2: rule accumulation ----------------
// blockDim 256 = 8 warps x 32 lanes. lane = sample within tile; warp = rule chunk.
// Each warp: 256 contiguous rules (top digits j0..j3 fixed -> one prefix product).
__global__ __launch_bounds__(256) void rules_kernel(const float* __restrict__ W,
                                                    const float* __restrict__ b) {
    __shared__ float s_part[8][32][12];

    int lane = threadIdx.x & 31;
    int w = threadIdx.x >> 5;
    int n = blockIdx.x * 32 + lane;
    int chunk = blockIdx.y * 8 + w;  // 0..255
    int rbase = chunk << 8;

    const float* mg = g_mg + n * 32;
    float prefix = mg[0 + ((chunk >> 6) & 3)]
                 * mg[4 + ((chunk >> 4) & 3)]
                 * mg[8 + ((chunk >> 2) & 3)]
                 * mg[12 + (chunk & 3)];

    float mg4[4], mg5[4], mg6[4], mg7[4];
#pragma unroll
    for (int j = 0; j < 4; j++) {
        mg4[j] = mg[16 + j];
        mg5[j] = mg[20 + j];
        mg6[j] = mg[24 + j];
        mg7[j] = mg[28 + j];
    }

    unsigned long long a01 = 0ull, a23 = 0ull, a45 = 0ull, a67 = 0ull;
    float ab = 0.f;

#pragma unroll
    for (int j4 = 0; j4 < 4; j4++) {
        float p4 = prefix * mg4[j4];
#pragma unroll
        for (int j5 = 0; j5 < 4; j5++) {
            float p5 = p4 * mg5[j5];
            int rb = rbase + j4 * 64 + j5 * 16;  // 16 rules, contiguous
            const ulonglong2* Wp = reinterpret_cast<const ulonglong2*>(W + (size_t)rb * 8);
            const float4* bp = reinterpret_cast<const float4*>(b + rb);
#pragma unroll
            for (int j6 = 0; j6 < 4; j6++) {
                float p6 = p5 * mg6[j6];
                float4 bv = bp[j6];
                float bb[4] = {bv.x, bv.y, bv.z, bv.w};
#pragma unroll
                for (int j7 = 0; j7 < 4; j7++) {
                    int ri = j6 * 4 + j7;
                    float f = p6 * mg7[j7];
                    unsigned long long f2 = pack2(f);
                    ulonglong2 q0 = Wp[ri * 2];
                    ulonglong2 q1 = Wp[ri * 2 + 1];
                    fma2(a01, f2, q0.x);
                    fma2(a23, f2, q0.y);
                    fma2(a45, f2, q1.x);
                    fma2(a67, f2, q1.y);
                    ab = fmaf(f, bb[j7], ab);
                }
            }
        }
    }

    // spill warp partials to smem
    float2 u01 = *reinterpret_cast<float2*>(&a01);
    float2 u23 = *reinterpret_cast<float2*>(&a23);
    float2 u45 = *reinterpret_cast<float2*>(&a45);
    float2 u67 = *reinterpret_cast<float2*>(&a67);
    s_part[w][lane][0] = u01.x;
    s_part[w][lane][1] = u01.y;
    s_part[w][lane][2] = u23.x;
    s_part[w][lane][3] = u23.y;
    s_part[w][lane][4] = u45.x;
    s_part[w][lane][5] = u45.y;
    s_part[w][lane][6] = u67.x;
    s_part[w][lane][7] = u67.y;
    s_part[w][lane][8] = ab;
    __syncthreads();

    // deterministic 8-warp reduction, write per-(rule-group) partials
    for (int idx = threadIdx.x; idx < 32 * 9; idx += 256) {
        int s = idx / 9;
        int k = idx - s * 9;
        float acc = 0.f;
#pragma unroll
        for (int ww = 0; ww < 8; ww++) acc += s_part[ww][s][k];
        int nn = blockIdx.x * 32 + s;
        g_part[(blockIdx.y * NSAMP + nn) * 12 + k] = acc;
    }
}

// ---------------- kernel 3: finalize ----------------
__global__ void final_kernel(const float* __restrict__ x, float* __restrict__ out) {
    int n = blockIdx.x * blockDim.x + threadIdx.x;
    if (n >= NSAMP) return;
    float A[9];
#pragma unroll
    for (int k = 0; k < 9; k++) A[k] = 0.f;
    for (int gy = 0; gy < GY; gy++) {
        const float* p = g_part + (gy * NSAMP + n) * 12;
#pragma unroll
        for (int k = 0; k < 9; k++) A[k] += p[k];
    }
    float o = A[8];
#pragma unroll
    for (int m = 0; m < MDIM; m++) o = fmaf(x[n * MDIM + m], A[m], o);
    out[n] = o;
}

extern "C" void kernel_launch(void* const* d_in, const int* in_sizes, int n_in,
                              void* d_out, int out_size) {
    const float* x      = (const float*)d_in[0];
    const float* center = (const float*)d_in[1];
    const float* sigma  = (const float*)d_in[2];
    const float* W      = (const float*)d_in[3];
    const float* b      = (const float*)d_in[4];
    float* out = (float*)d_out;

    mg_kernel<<<4, 256>>>(x, center, sigma);
    dim3 grid(STILES, GY);
    rules_kernel<<<grid, 256>>>(W, b);
    final_kernel<<<4, 256>>>(x, out);
}

// round 3
// speedup vs baseline: 1.0360x; 1.0360x over previous
#include <cuda_runtime.h>

// TSK fuzzy system: out[n] = sum_r fg_bar[n,r] * (x[n]·W[r] + b[r])
// Separable normalization: fg_bar[n,r] = prod_m mgn[n,m,digit_m(r)] with
// mgn = mg / sum_j mg per (n,m). Then out[n] = x[n]·A[n] + c[n] with
// A[n] = sum_r fg_bar[n,r] W[r],  c[n] = sum_r fg_bar[n,r] b[r].

#define NSAMP 1024
#define MDIM 8
#define NMF4 4
#define RRULES 65536
#define GYY 64     // rule-chunk groups (grid.y); 4 warps/CTA, each warp 256 rules
#define TILES 16   // sample tiles of 64 (2 samples per lane)

__device__ float g_mg[NSAMP * 32];             // normalized memberships [n][m*4+j]
__device__ float g_part[GYY * NSAMP * 12];     // partials [gy][n][12] (9 used)

// ---------------- kernel 1: normalized memberships ----------------
__global__ void mg_kernel(const float* __restrict__ x,
                          const float* __restrict__ center,
                          const float* __restrict__ sigma) {
    int n = blockIdx.x * blockDim.x + threadIdx.x;
    if (n >= NSAMP) return;
#pragma unroll
    for (int m = 0; m < MDIM; m++) {
        float xv = x[n * MDIM + m];
        float e[NMF4];
        float s = 0.f;
#pragma unroll
        for (int j = 0; j < NMF4; j++) {
            float d = xv - center[m * NMF4 + j];
            float sg = sigma[m * NMF4 + j];
            e[j] = expf(-d * d * 0.5f * sg * sg);
            s += e[j];
        }
        float inv = 1.0f / s;
#pragma unroll
        for (int j = 0; j < NMF4; j++)
            g_mg[n * 32 + m * 4 + j] = e[j] * inv;
    }
}

// ---------------- packed f32x2 helpers (Blackwell) ----------------
typedef unsigned long long ull;
__device__ __forceinline__ ull pack2(float f) {
    ull r;
    asm("mov.b64 %0, {%1, %1};" : "=l"(r) : "f"(f));
    return r;
}
__device__ __forceinline__ ull mul2(ull a, ull b) {
    ull d;
    asm("mul.rn.f32x2 %0, %1, %2;" : "=l"(d) : "l"(a), "l"(b));
    return d;
}
__device__ __forceinline__ void fma2(ull& d, ull a, ull b) {
    asm("fma.rn.f32x2 %0, %1, %2, %0;" : "+l"(d) : "l"(a), "l"(b));
}
__device__ __forceinline__ float lo32(ull v) {
    return __uint_as_float((unsigned)v);
}

// ---------------- kernel 2: rule accumulation ----------------
// block = 128 threads = 4 warps. Lane = sample pair (n0 = tile*64+lane, n1 = n0+32).
// Each warp owns one 256-rule chunk; W/b loads broadcast across lanes and are
// amortized over 2 samples per lane.
__global__ __launch_bounds__(128) void rules_kernel(const float* __restrict__ W,
                                                    const float* __restrict__ b) {
    __shared__ float s_part[4][64][12];

    int lane = threadIdx.x & 31;
    int w = threadIdx.x >> 5;
    int n0 = blockIdx.x * 64 + lane;
    int n1 = n0 + 32;
    int chunk = blockIdx.y * 4 + w;   // 0..255
    int rbase = chunk << 8;

    const float* mgA = g_mg + n0 * 32;
    const float* mgB = g_mg + n1 * 32;

    int d0 = (chunk >> 6) & 3, d1 = (chunk >> 4) & 3, d2 = (chunk >> 2) & 3, d3 = chunk & 3;
    float preA = mgA[d0] * mgA[4 + d1] * mgA[8 + d2] * mgA[12 + d3];
    float preB = mgB[d0] * mgB[4 + d1] * mgB[8 + d2] * mgB[12 + d3];

    float m4A[4], m5A[4], m6A[4], m4B[4], m5B[4], m6B[4];
    ull pm7A[4], pm7B[4];
#pragma unroll
    for (int j = 0; j < 4; j++) {
        m4A[j] = mgA[16 + j]; m5A[j] = mgA[20 + j]; m6A[j] = mgA[24 + j];
        m4B[j] = mgB[16 + j]; m5B[j] = mgB[20 + j]; m6B[j] = mgB[24 + j];
        pm7A[j] = pack2(mgA[28 + j]);
        pm7B[j] = pack2(mgB[28 + j]);
    }

    ull aA[4] = {0ull, 0ull, 0ull, 0ull};
    ull aB[4] = {0ull, 0ull, 0ull, 0ull};
    float cA = 0.f, cB = 0.f;

#pragma unroll 1
    for (int j4 = 0; j4 < 4; j4++) {
        float p4A = preA * m4A[j4];
        float p4B = preB * m4B[j4];
#pragma unroll
        for (int j5 = 0; j5 < 4; j5++) {
            float p5A = p4A * m5A[j5];
            float p5B = p4B * m5B[j5];
            int rb = rbase + j4 * 64 + j5 * 16;   // 16 contiguous rules
            const ulonglong2* Wp = reinterpret_cast<const ulonglong2*>(W + (size_t)rb * 8);
            const float4* bp = reinterpret_cast<const float4*>(b + rb);
#pragma unroll
            for (int j6 = 0; j6 < 4; j6++) {
                ull pp6A = pack2(p5A * m6A[j6]);
                ull pp6B = pack2(p5B * m6B[j6]);
                float4 bv = bp[j6];
                float bb[4] = {bv.x, bv.y, bv.z, bv.w};
#pragma unroll
                for (int j7 = 0; j7 < 4; j7++) {
                    int ri = j6 * 4 + j7;
                    ulonglong2 q0 = Wp[ri * 2];
                    ulonglong2 q1 = Wp[ri * 2 + 1];
                    ull fA = mul2(pp6A, pm7A[j7]);
                    fma2(aA[0], fA, q0.x);
                    fma2(aA[1], fA, q0.y);
                    fma2(aA[2], fA, q1.x);
                    fma2(aA[3], fA, q1.y);
                    cA = fmaf(lo32(fA), bb[j7], cA);
                    ull fB = mul2(pp6B, pm7B[j7]);
                    fma2(aB[0], fB, q0.x);
                    fma2(aB[1], fB, q0.y);
                    fma2(aB[2], fB, q1.x);
                    fma2(aB[3], fB, q1.y);
                    cB = fmaf(lo32(fB), bb[j7], cB);
                }
            }
        }
    }

    // spill warp partials to smem: sample slot = lane (A) and lane+32 (B)
#pragma unroll
    for (int k = 0; k < 4; k++) {
        float2 uA = *reinterpret_cast<float2*>(&aA[k]);
        float2 uB = *reinterpret_cast<float2*>(&aB[k]);
        s_part[w][lane][2 * k]     = uA.x;
        s_part[w][lane][2 * k + 1] = uA.y;
        s_part[w][lane + 32][2 * k]     = uB.x;
        s_part[w][lane + 32][2 * k + 1] = uB.y;
    }
    s_part[w][lane][8] = cA;
    s_part[w][lane + 32][8] = cB;
    __syncthreads();

    // deterministic 4-warp reduction -> per-(gy, sample) partials
    for (int idx = threadIdx.x; idx < 64 * 9; idx += 128) {
        int s = idx / 9;
        int k = idx - s * 9;
        float acc = s_part[0][s][k] + s_part[1][s][k] + s_part[2][s][k] + s_part[3][s][k];
        int nn = blockIdx.x * 64 + s;
        g_part[(blockIdx.y * NSAMP + nn) * 12 + k] = acc;
    }
}

// ---------------- kernel 3: finalize ----------------
__global__ void final_kernel(const float* __restrict__ x, float* __restrict__ out) {
    int n = blockIdx.x * blockDim.x + threadIdx.x;
    if (n >= NSAMP) return;
    float A[9];
#pragma unroll
    for (int k = 0; k < 9; k++) A[k] = 0.f;
    for (int gy = 0; gy < GYY; gy++) {
        const float4* p = reinterpret_cast<const float4*>(g_part + (gy * NSAMP + n) * 12);
        float4 u = p[0], v = p[1], t = p[2];
        A[0] += u.x; A[1] += u.y; A[2] += u.z; A[3] += u.w;
        A[4] += v.x; A[5] += v.y; A[6] += v.z; A[7] += v.w;
        A[8] += t.x;
    }
    float o = A[8];
#pragma unroll
    for (int m = 0; m < MDIM; m++) o = fmaf(x[n * MDIM + m], A[m], o);
    out[n] = o;
}

extern "C" void kernel_launch(void* const* d_in, const int* in_sizes, int n_in,
                              void* d_out, int out_size) {
    const float* x      = (const float*)d_in[0];
    const float* center = (const float*)d_in[1];
    const float* sigma  = (const float*)d_in[2];
    const float* W      = (const float*)d_in[3];
    const float* b      = (const float*)d_in[4];
    float* out = (float*)d_out;

    mg_kernel<<<16, 64>>>(x, center, sigma);
    dim3 grid(TILES, GYY);
    rules_kernel<<<grid, 128>>>(W, b);
    final_kernel<<<8, 128>>>(x, out);
}

// round 4
// speedup vs baseline: 1.1084x; 1.0699x over previous
#include <cuda_runtime.h>

// TSK fuzzy system: out[n] = sum_r fg_bar[n,r] * (x[n]·W[r] + b[r])
// Separable normalization: fg_bar[n,r] = prod_m mgn[n,m,digit_m(r)],
// mgn = mg / sum_j mg per (n,m). out[n] = x[n]·A[n] + c[n],
// A[n] = sum_r fg_bar W[r], c[n] = sum_r fg_bar b[r].
// f32x2 lanes packed over a PAIR OF SAMPLES; W/b staged in smem as {w,w} pairs.

#define NSAMP 1024
#define NGROUP 128   // rule groups of 512 rules (grid.y)
#define TILES 16     // sample tiles of 64 (grid.x); 2 samples per lane

typedef unsigned long long ull;

__device__ float g_mg[NSAMP * 32];                 // normalized memberships [n][m*4+j]
__device__ float g_part[NGROUP * 12 * NSAMP];      // partials [g][k][n], k<9 used

// ---------------- packed f32x2 helpers ----------------
__device__ __forceinline__ ull pack2(float f) {
    ull r; asm("mov.b64 %0, {%1, %1};" : "=l"(r) : "f"(f)); return r;
}
__device__ __forceinline__ ull pack2f(float a, float b) {
    ull r; asm("mov.b64 %0, {%1, %2};" : "=l"(r) : "f"(a), "f"(b)); return r;
}
__device__ __forceinline__ ull mul2(ull a, ull b) {
    ull d; asm("mul.rn.f32x2 %0, %1, %2;" : "=l"(d) : "l"(a), "l"(b)); return d;
}
__device__ __forceinline__ void fma2(ull& d, ull a, ull b) {
    asm("fma.rn.f32x2 %0, %1, %2, %0;" : "+l"(d) : "l"(a), "l"(b));
}
__device__ __forceinline__ void unpack2(ull v, float& lo, float& hi) {
    asm("mov.b64 {%0, %1}, %2;" : "=f"(lo), "=f"(hi) : "l"(v));
}

// ---------------- kernel 1: normalized memberships ----------------
// 8192 threads, one (n, m) pair each.
__global__ void mg_kernel(const float* __restrict__ x,
                          const float* __restrict__ center,
                          const float* __restrict__ sigma) {
    int id = blockIdx.x * 128 + threadIdx.x;
    int n = id >> 3, m = id & 7;
    float xv = x[n * 8 + m];
    float e[4], s = 0.f;
#pragma unroll
    for (int j = 0; j < 4; j++) {
        float d = xv - center[m * 4 + j];
        float sg = sigma[m * 4 + j];
        e[j] = __expf(-0.5f * d * d * sg * sg);
        s += e[j];
    }
    float inv = 1.0f / s;
    float4 o = make_float4(e[0] * inv, e[1] * inv, e[2] * inv, e[3] * inv);
    *reinterpret_cast<float4*>(&g_mg[n * 32 + m * 4]) = o;
}

// ---------------- kernel 2: rule accumulation ----------------
// block = 128 threads = 4 warps. CTA: 512 rules (one group), 64 samples.
// Warp w handles local rules [w*128, w*128+128) for all 64 samples (2/lane).
// smem: sm[rule*8+k] = {W[r][k], W[r][k]} pairs (512*8 ull = 32KB),
//       sm[4096+rule] = {b[r], b[r]} (4KB).
__global__ __launch_bounds__(128) void rules_kernel(const float* __restrict__ W,
                                                    const float* __restrict__ b) {
    __shared__ __align__(16) ull sm[4608];

    int tid = threadIdx.x, lane = tid & 31, w = tid >> 5;
    int gy = blockIdx.y;

    // cooperative fill: W (4096 floats) + b (512 floats), duplicated pairs
    const float4* Wg = reinterpret_cast<const float4*>(W + (size_t)gy * 512 * 8);
#pragma unroll 2
    for (int i = tid; i < 1024; i += 128) {
        float4 v = Wg[i];
        int base = i * 4;
        sm[base + 0] = pack2(v.x); sm[base + 1] = pack2(v.y);
        sm[base + 2] = pack2(v.z); sm[base + 3] = pack2(v.w);
    }
    {
        const float4* bg = reinterpret_cast<const float4*>(b + (size_t)gy * 512);
        int i = tid;  // 128 float4 = 512 floats, exactly one per thread
        float4 v = bg[i];
        int base = 4096 + i * 4;
        sm[base + 0] = pack2(v.x); sm[base + 1] = pack2(v.y);
        sm[base + 2] = pack2(v.z); sm[base + 3] = pack2(v.w);
    }

    // per-thread sample pair
    int n0 = blockIdx.x * 64 + lane;
    int n1 = n0 + 32;
    const float* mgA = g_mg + n0 * 32;
    const float* mgB = g_mg + n1 * 32;

    // warp's rule span: global base rg0, top digits fixed
    int rg0 = gy * 512 + w * 128;
    int chunk = rg0 >> 8;   // digits j0..j3
    int d0 = (chunk >> 6) & 3, d1 = (chunk >> 4) & 3, d2 = (chunk >> 2) & 3, d3 = chunk & 3;
    float preA = mgA[d0] * mgA[4 + d1] * mgA[8 + d2] * mgA[12 + d3];
    float preB = mgB[d0] * mgB[4 + d1] * mgB[8 + d2] * mgB[12 + d3];
    ull pre = pack2f(preA, preB);

    int j4b = (w & 1) * 2;   // j4 takes 2 values within this warp's 128 rules
    ull pm4[2], pm5[4], pm6[4], pm7[4];
#pragma unroll
    for (int j = 0; j < 2; j++) pm4[j] = pack2f(mgA[16 + j4b + j], mgB[16 + j4b + j]);
#pragma unroll
    for (int j = 0; j < 4; j++) {
        pm5[j] = pack2f(mgA[20 + j], mgB[20 + j]);
        pm6[j] = pack2f(mgA[24 + j], mgB[24 + j]);
        pm7[j] = pack2f(mgA[28 + j], mgB[28 + j]);
    }

    __syncthreads();   // smem W/b ready

    ull acc[8] = {0ull, 0ull, 0ull, 0ull, 0ull, 0ull, 0ull, 0ull};
    ull cacc = 0ull;
    int rloc = w * 128;

#pragma unroll 1
    for (int j4 = 0; j4 < 2; j4++) {
        ull p4 = mul2(pre, pm4[j4]);
#pragma unroll 1
        for (int j5 = 0; j5 < 4; j5++) {
            ull p5 = mul2(p4, pm5[j5]);
            int rb = rloc + j4 * 64 + j5 * 16;   // 16 contiguous rules
            const ulonglong2* wp = reinterpret_cast<const ulonglong2*>(&sm[rb * 8]);
            const ull* bp = &sm[4096 + rb];
#pragma unroll
            for (int j6 = 0; j6 < 4; j6++) {
                ull p6 = mul2(p5, pm6[j6]);
#pragma unroll
                for (int j7 = 0; j7 < 4; j7++) {
                    int ri = j6 * 4 + j7;
                    ull f = mul2(p6, pm7[j7]);
                    ulonglong2 q0 = wp[ri * 4 + 0];
                    ulonglong2 q1 = wp[ri * 4 + 1];
                    ulonglong2 q2 = wp[ri * 4 + 2];
                    ulonglong2 q3 = wp[ri * 4 + 3];
                    fma2(acc[0], f, q0.x); fma2(acc[1], f, q0.y);
                    fma2(acc[2], f, q1.x); fma2(acc[3], f, q1.y);
                    fma2(acc[4], f, q2.x); fma2(acc[5], f, q2.y);
                    fma2(acc[6], f, q3.x); fma2(acc[7], f, q3.y);
                    fma2(cacc, f, bp[ri]);
                }
            }
        }
    }

    // reduction: reuse smem as float buffer [warp][sample 0..63][12]
    __syncthreads();
    float* red = reinterpret_cast<float*>(sm);
#pragma unroll
    for (int k = 0; k < 8; k++) {
        float lo, hi; unpack2(acc[k], lo, hi);
        red[(w * 64 + lane) * 12 + k] = lo;
        red[(w * 64 + lane + 32) * 12 + k] = hi;
    }
    {
        float lo, hi; unpack2(cacc, lo, hi);
        red[(w * 64 + lane) * 12 + 8] = lo;
        red[(w * 64 + lane + 32) * 12 + 8] = hi;
    }
    __syncthreads();

    // deterministic 4-warp sum -> g_part[g][k][n] (coalesced: consecutive tid = consecutive s)
#pragma unroll 1
    for (int idx = tid; idx < 9 * 64; idx += 128) {
        int k = idx >> 6;
        int s = idx & 63;
        float a = red[(0 * 64 + s) * 12 + k] + red[(1 * 64 + s) * 12 + k]
                + red[(2 * 64 + s) * 12 + k] + red[(3 * 64 + s) * 12 + k];
        int n = blockIdx.x * 64 + s;
        g_part[(gy * 12 + k) * NSAMP + n] = a;
    }
}

// ---------------- kernel 3: finalize ----------------
__global__ void final_kernel(const float* __restrict__ x, float* __restrict__ out) {
    int n = blockIdx.x * 32 + threadIdx.x;
    float A[9];
#pragma unroll
    for (int k = 0; k < 9; k++) A[k] = 0.f;
#pragma unroll 4
    for (int g = 0; g < NGROUP; g++) {
#pragma unroll
        for (int k = 0; k < 9; k++) A[k] += g_part[(g * 12 + k) * NSAMP + n];
    }
    float o = A[8];
#pragma unroll
    for (int m = 0; m < 8; m++) o = fmaf(x[n * 8 + m], A[m], o);
    out[n] = o;
}

extern "C" void kernel_launch(void* const* d_in, const int* in_sizes, int n_in,
                              void* d_out, int out_size) {
    const float* x      = (const float*)d_in[0];
    const float* center = (const float*)d_in[1];
    const float* sigma  = (const float*)d_in[2];
    const float* W      = (const float*)d_in[3];
    const float* b      = (const float*)d_in[4];
    float* out = (float*)d_out;

    mg_kernel<<<64, 128>>>(x, center, sigma);
    dim3 grid(TILES, NGROUP);
    rules_kernel<<<grid, 128>>>(W, b);
    final_kernel<<<32, 32>>>(x, out);
}

// round 5
// speedup vs baseline: 2.2460x; 2.0264x over previous
#include <cuda_runtime.h>

// TSK fuzzy system, single fused kernel.
// out[n] = sum_r fg_bar[n,r]*(x[n]·W[r]+b[r]);  separable normalization:
// fg_bar[n,r] = prod_m mgn[n,m,digit_m(r)], mgn = mg/sum_j mg.
// out[n] = x[n]·A[n]+c[n], A[n]=sum_r fg_bar W[r], c[n]=sum_r fg_bar b[r].
// f32x2 packs a PAIR of samples; each lane carries TWO pairs (4 samples).

#define NSAMP 1024
#define NGROUP 128          // grid.y: rule groups of 512
#define TILES 8             // grid.x: sample tiles of 128
#define SM_W_BYTES 36864    // 4608 ull: W pairs (4096) + b pairs (512)
#define SM_MG_BYTES 16896   // 128 rows * 33 floats (padded, conflict-free)
#define SMEM_BYTES (SM_W_BYTES + SM_MG_BYTES)

typedef unsigned long long ull;

__device__ float g_part[NGROUP * 12 * NSAMP];  // [g][k][n], k<9 used
__device__ int g_cnt[TILES];                    // zero-init; reset by finisher

__device__ __forceinline__ ull pack2(float f) {
    ull r; asm("mov.b64 %0, {%1, %1};" : "=l"(r) : "f"(f)); return r;
}
__device__ __forceinline__ ull pack2f(float a, float b) {
    ull r; asm("mov.b64 %0, {%1, %2};" : "=l"(r) : "f"(a), "f"(b)); return r;
}
__device__ __forceinline__ ull mul2(ull a, ull b) {
    ull d; asm("mul.rn.f32x2 %0, %1, %2;" : "=l"(d) : "l"(a), "l"(b)); return d;
}
__device__ __forceinline__ void fma2(ull& d, ull a, ull b) {
    asm("fma.rn.f32x2 %0, %1, %2, %0;" : "+l"(d) : "l"(a), "l"(b));
}
__device__ __forceinline__ void unpack2(ull v, float& lo, float& hi) {
    asm("mov.b64 {%0, %1}, %2;" : "=f"(lo), "=f"(hi) : "l"(v));
}

__global__ __launch_bounds__(128) void tsk_kernel(
    const float* __restrict__ x, const float* __restrict__ center,
    const float* __restrict__ sigma, const float* __restrict__ W,
    const float* __restrict__ b, float* __restrict__ out)
{
    extern __shared__ __align__(16) unsigned char smraw[];
    ull* sm = reinterpret_cast<ull*>(smraw);                    // W/b pairs
    float* s_mg = reinterpret_cast<float*>(smraw + SM_W_BYTES); // memberships

    int tid = threadIdx.x, lane = tid & 31, w = tid >> 5;
    int gy = blockIdx.y, tile = blockIdx.x;

    // ---- stage W (512 rules x 8) and b (512) as duplicated {v,v} pairs ----
    const float4* Wg = reinterpret_cast<const float4*>(W + (size_t)gy * 4096);
#pragma unroll 2
    for (int i = tid; i < 1024; i += 128) {
        float4 v = Wg[i];
        sm[i * 4 + 0] = pack2(v.x); sm[i * 4 + 1] = pack2(v.y);
        sm[i * 4 + 2] = pack2(v.z); sm[i * 4 + 3] = pack2(v.w);
    }
    {
        const float4* bg = reinterpret_cast<const float4*>(b + gy * 512);
        float4 v = bg[tid];
        sm[4096 + tid * 4 + 0] = pack2(v.x); sm[4096 + tid * 4 + 1] = pack2(v.y);
        sm[4096 + tid * 4 + 2] = pack2(v.z); sm[4096 + tid * 4 + 3] = pack2(v.w);
    }

    // ---- compute normalized memberships for this tile's 128 samples ----
    {
        int s = tile * 128 + tid;
        float* row = s_mg + tid * 33;
#pragma unroll
        for (int m = 0; m < 8; m++) {
            float xv = x[s * 8 + m];
            float e[4], sum = 0.f;
#pragma unroll
            for (int j = 0; j < 4; j++) {
                float d = xv - center[m * 4 + j];
                float sg = sigma[m * 4 + j];
                e[j] = __expf(-0.5f * d * d * sg * sg);
                sum += e[j];
            }
            float inv = 1.0f / sum;
#pragma unroll
            for (int j = 0; j < 4; j++) row[m * 4 + j] = e[j] * inv;
        }
    }
    __syncthreads();

    // ---- per-thread membership packs: samples lane, +32, +64, +96 ----
    const float* r0 = s_mg + lane * 33;
    const float* r1 = s_mg + (lane + 32) * 33;
    const float* r2 = s_mg + (lane + 64) * 33;
    const float* r3 = s_mg + (lane + 96) * 33;

    int chunk = gy * 2 + (w >> 1);  // digits j0..j3 of this warp's rules
    int d0 = (chunk >> 6) & 3, d1 = (chunk >> 4) & 3, d2 = (chunk >> 2) & 3, d3 = chunk & 3;
    ull preP = pack2f(r0[d0] * r0[4 + d1] * r0[8 + d2] * r0[12 + d3],
                      r1[d0] * r1[4 + d1] * r1[8 + d2] * r1[12 + d3]);
    ull preQ = pack2f(r2[d0] * r2[4 + d1] * r2[8 + d2] * r2[12 + d3],
                      r3[d0] * r3[4 + d1] * r3[8 + d2] * r3[12 + d3]);

    int j4b = (w & 1) * 2;
    ull pm4P[2], pm5P[4], pm6P[4], pm7P[4];
    ull pm4Q[2], pm5Q[4], pm6Q[4], pm7Q[4];
#pragma unroll
    for (int j = 0; j < 2; j++) {
        pm4P[j] = pack2f(r0[16 + j4b + j], r1[16 + j4b + j]);
        pm4Q[j] = pack2f(r2[16 + j4b + j], r3[16 + j4b + j]);
    }
#pragma unroll
    for (int j = 0; j < 4; j++) {
        pm5P[j] = pack2f(r0[20 + j], r1[20 + j]);
        pm6P[j] = pack2f(r0[24 + j], r1[24 + j]);
        pm7P[j] = pack2f(r0[28 + j], r1[28 + j]);
        pm5Q[j] = pack2f(r2[20 + j], r3[20 + j]);
        pm6Q[j] = pack2f(r2[24 + j], r3[24 + j]);
        pm7Q[j] = pack2f(r2[28 + j], r3[28 + j]);
    }

    ull aP[8] = {0,0,0,0,0,0,0,0}, aQ[8] = {0,0,0,0,0,0,0,0};
    ull cP = 0ull, cQ = 0ull;

    // ---- main loop: 128 rules per warp, 4 samples per lane ----
#pragma unroll 1
    for (int j4 = 0; j4 < 2; j4++) {
        ull p4P = mul2(preP, pm4P[j4]);
        ull p4Q = mul2(preQ, pm4Q[j4]);
#pragma unroll 1
        for (int j5 = 0; j5 < 4; j5++) {
            ull p5P = mul2(p4P, pm5P[j5]);
            ull p5Q = mul2(p4Q, pm5Q[j5]);
            int rb = w * 128 + j4 * 64 + j5 * 16;
            const ulonglong2* wp = reinterpret_cast<const ulonglong2*>(&sm[rb * 8]);
            const ull* bp = &sm[4096 + rb];
#pragma unroll
            for (int j6 = 0; j6 < 4; j6++) {
                ull p6P = mul2(p5P, pm6P[j6]);
                ull p6Q = mul2(p5Q, pm6Q[j6]);
#pragma unroll
                for (int j7 = 0; j7 < 4; j7++) {
                    int ri = j6 * 4 + j7;
                    ull fP = mul2(p6P, pm7P[j7]);
                    ull fQ = mul2(p6Q, pm7Q[j7]);
                    ulonglong2 q0 = wp[ri * 4 + 0];
                    ulonglong2 q1 = wp[ri * 4 + 1];
                    ulonglong2 q2 = wp[ri * 4 + 2];
                    ulonglong2 q3 = wp[ri * 4 + 3];
                    ull bb = bp[ri];
                    fma2(aP[0], fP, q0.x); fma2(aQ[0], fQ, q0.x);
                    fma2(aP[1], fP, q0.y); fma2(aQ[1], fQ, q0.y);
                    fma2(aP[2], fP, q1.x); fma2(aQ[2], fQ, q1.x);
                    fma2(aP[3], fP, q1.y); fma2(aQ[3], fQ, q1.y);
                    fma2(aP[4], fP, q2.x); fma2(aQ[4], fQ, q2.x);
                    fma2(aP[5], fP, q2.y); fma2(aQ[5], fQ, q2.y);
                    fma2(aP[6], fP, q3.x); fma2(aQ[6], fQ, q3.x);
                    fma2(aP[7], fP, q3.y); fma2(aQ[7], fQ, q3.y);
                    fma2(cP, fP, bb);      fma2(cQ, fQ, bb);
                }
            }
        }
    }

    // ---- cross-warp reduction (reuse W smem region, now dead) ----
    __syncthreads();
    float* red = reinterpret_cast<float*>(smraw);  // [warp][sample128][12]
#pragma unroll
    for (int k = 0; k < 8; k++) {
        float lo, hi;
        unpack2(aP[k], lo, hi);
        red[(w * 128 + lane) * 12 + k] = lo;
        red[(w * 128 + lane + 32) * 12 + k] = hi;
        unpack2(aQ[k], lo, hi);
        red[(w * 128 + lane + 64) * 12 + k] = lo;
        red[(w * 128 + lane + 96) * 12 + k] = hi;
    }
    {
        float lo, hi;
        unpack2(cP, lo, hi);
        red[(w * 128 + lane) * 12 + 8] = lo;
        red[(w * 128 + lane + 32) * 12 + 8] = hi;
        unpack2(cQ, lo, hi);
        red[(w * 128 + lane + 64) * 12 + 8] = lo;
        red[(w * 128 + lane + 96) * 12 + 8] = hi;
    }
    __syncthreads();

#pragma unroll 1
    for (int idx = tid; idx < 9 * 128; idx += 128) {
        int k = idx >> 7;
        int s = idx & 127;
        float a = red[(0 * 128 + s) * 12 + k] + red[(1 * 128 + s) * 12 + k]
                + red[(2 * 128 + s) * 12 + k] + red[(3 * 128 + s) * 12 + k];
        g_part[(gy * 12 + k) * NSAMP + tile * 128 + s] = a;
    }

    // ---- fused finalize: last CTA of this tile reduces over all groups ----
    __threadfence();
    __syncthreads();
    __shared__ int isLast;
    if (tid == 0) {
        int c = atomicAdd(&g_cnt[tile], 1);
        isLast = (c == NGROUP - 1) ? 1 : 0;
    }
    __syncthreads();
    if (isLast) {
        __threadfence();
        int n = tile * 128 + tid;
        float A[9];
#pragma unroll
        for (int k = 0; k < 9; k++) A[k] = 0.f;
#pragma unroll 4
        for (int g = 0; g < NGROUP; g++) {
#pragma unroll
            for (int k = 0; k < 9; k++) A[k] += g_part[(g * 12 + k) * NSAMP + n];
        }
        float o = A[8];
#pragma unroll
        for (int m = 0; m < 8; m++) o = fmaf(x[n * 8 + m], A[m], o);
        out[n] = o;
        if (tid == 0) g_cnt[tile] = 0;  // reset for next replay (all arrivals done)
    }
}

extern "C" void kernel_launch(void* const* d_in, const int* in_sizes, int n_in,
                              void* d_out, int out_size) {
    const float* x      = (const float*)d_in[0];
    const float* center = (const float*)d_in[1];
    const float* sigma  = (const float*)d_in[2];
    const float* W      = (const float*)d_in[3];
    const float* b      = (const float*)d_in[4];
    float* out = (float*)d_out;

    cudaFuncSetAttribute(tsk_kernel, cudaFuncAttributeMaxDynamicSharedMemorySize,
                         SMEM_BYTES);
    dim3 grid(TILES, NGROUP);
    tsk_kernel<<<grid, 128, SMEM_BYTES>>>(x, center, sigma, W, b, out);
}

// round 6
// speedup vs baseline: 2.2473x; 1.0006x over previous
#include <cuda_runtime.h>

// TSK fuzzy system, single fused kernel.
// out[n] = sum_r fg_bar[n,r]*(x[n]·W[r]+b[r]);  separable normalization:
// fg_bar[n,r] = prod_m mgn[n,m,digit_m(r)], mgn = mg/sum_j mg.
// out[n] = x[n]·A[n]+c[n], A[n]=sum_r fg_bar W[r], c[n]=sum_r fg_bar b[r].
// f32x2 lanes pack a PAIR OF ADJACENT RULES (W stored once, no duplication).
// Each lane carries 2 samples (two independent accumulator sets for ILP).

#define NSAMP 1024
#define NGROUP 128   // grid.y: rule groups of 512
#define TILES 16     // grid.x: sample tiles of 64

typedef unsigned long long ull;

__device__ float g_part[NGROUP * 9 * NSAMP];  // [g][k][n]
__device__ int g_cnt[TILES];                  // zero-init; reset by finisher

__device__ __forceinline__ ull pack2(float f) {
    ull r; asm("mov.b64 %0, {%1, %1};" : "=l"(r) : "f"(f)); return r;
}
__device__ __forceinline__ ull pack2f(float a, float b) {
    ull r; asm("mov.b64 %0, {%1, %2};" : "=l"(r) : "f"(a), "f"(b)); return r;
}
__device__ __forceinline__ ull mul2(ull a, ull b) {
    ull d; asm("mul.rn.f32x2 %0, %1, %2;" : "=l"(d) : "l"(a), "l"(b)); return d;
}
__device__ __forceinline__ void fma2(ull& d, ull a, ull b) {
    asm("fma.rn.f32x2 %0, %1, %2, %0;" : "+l"(d) : "l"(a), "l"(b));
}
__device__ __forceinline__ void unpack2(ull v, float& lo, float& hi) {
    asm("mov.b64 {%0, %1}, %2;" : "=f"(lo), "=f"(hi) : "l"(v));
}

__global__ __launch_bounds__(128) void tsk_kernel(
    const float* __restrict__ x, const float* __restrict__ center,
    const float* __restrict__ sigma, const float* __restrict__ W,
    const float* __restrict__ b, float* __restrict__ out)
{
    // W pairs: smpair[p*8+k] = {W[2p][k], W[2p+1][k]}, p = 0..255 (512 rules)
    __shared__ __align__(16) ull smpair[2048];   // 16 KB
    __shared__ __align__(16) ull smb[256];       //  2 KB  {b[2p],b[2p+1]}
    __shared__ float s_mg[64 * 33];              // 8.4 KB memberships (padded)
    __shared__ float red[4][64][9];              // 9.2 KB cross-warp reduction
    __shared__ int isLast;

    int tid = threadIdx.x, lane = tid & 31, w = tid >> 5;
    int gy = blockIdx.y, tile = blockIdx.x;

    // ---- stage W (512 rules x 8) as adjacent-rule pairs ----
    const float4* Wg4 = reinterpret_cast<const float4*>(W + (size_t)gy * 4096);
#pragma unroll
    for (int i = tid; i < 512; i += 128) {
        int p = i >> 1, h = i & 1;               // pair p, k-half h
        float4 a = Wg4[(2 * p) * 2 + h];
        float4 c = Wg4[(2 * p + 1) * 2 + h];
        int base = p * 8 + h * 4;
        smpair[base + 0] = pack2f(a.x, c.x);
        smpair[base + 1] = pack2f(a.y, c.y);
        smpair[base + 2] = pack2f(a.z, c.z);
        smpair[base + 3] = pack2f(a.w, c.w);
    }
    {
        const float2* bg = reinterpret_cast<const float2*>(b + gy * 512);
        float2 v = bg[tid * 2], v2 = bg[tid * 2 + 1];
        smb[tid * 2] = pack2f(v.x, v.y);
        smb[tid * 2 + 1] = pack2f(v2.x, v2.y);
    }

    // ---- memberships: 2 threads per sample (4 dims each) ----
    {
        int s = tid & 63, mh = tid >> 6;         // mh: dims 0-3 or 4-7
        int n = tile * 64 + s;
        float4 xv4 = *reinterpret_cast<const float4*>(x + n * 8 + mh * 4);
        float xv[4] = {xv4.x, xv4.y, xv4.z, xv4.w};
#pragma unroll
        for (int mm = 0; mm < 4; mm++) {
            int m = mh * 4 + mm;
            float e[4], sum = 0.f;
#pragma unroll
            for (int j = 0; j < 4; j++) {
                float d = xv[mm] - center[m * 4 + j];
                float sg = sigma[m * 4 + j];
                e[j] = __expf(-0.5f * d * d * sg * sg);
                sum += e[j];
            }
            float inv = 1.0f / sum;
#pragma unroll
            for (int j = 0; j < 4; j++) s_mg[s * 33 + m * 4 + j] = e[j] * inv;
        }
    }
    __syncthreads();

    // ---- per-thread sample pair: n0 = tile*64+lane, n1 = n0+32 ----
    const float* r0 = s_mg + lane * 33;
    const float* r1 = s_mg + (lane + 32) * 33;

    // warp's 128 rules: digits j0..j3 from chunk, j4 in {j4b, j4b+1}
    int chunk = gy * 2 + (w >> 1);
    int d0 = (chunk >> 6) & 3, d1 = (chunk >> 4) & 3, d2 = (chunk >> 2) & 3, d3 = chunk & 3;
    float preA = r0[d0] * r0[4 + d1] * r0[8 + d2] * r0[12 + d3];
    float preB = r1[d0] * r1[4 + d1] * r1[8 + d2] * r1[12 + d3];
    int j4b = (w & 1) * 2;

    float pm4A[2], pm4B[2], pm5A[4], pm5B[4], pm6A[4], pm6B[4];
    ull pm7pA[2], pm7pB[2];
#pragma unroll
    for (int j = 0; j < 2; j++) {
        pm4A[j] = r0[16 + j4b + j];
        pm4B[j] = r1[16 + j4b + j];
    }
#pragma unroll
    for (int j = 0; j < 4; j++) {
        pm5A[j] = r0[20 + j]; pm6A[j] = r0[24 + j];
        pm5B[j] = r1[20 + j]; pm6B[j] = r1[24 + j];
    }
    pm7pA[0] = pack2f(r0[28], r0[29]); pm7pA[1] = pack2f(r0[30], r0[31]);
    pm7pB[0] = pack2f(r1[28], r1[29]); pm7pB[1] = pack2f(r1[30], r1[31]);

    ull aA[9] = {0,0,0,0,0,0,0,0,0};
    ull aB[9] = {0,0,0,0,0,0,0,0,0};

    // ---- main loop: 128 rules/warp as 64 rule-pairs, 2 samples/lane ----
#pragma unroll 1
    for (int j4 = 0; j4 < 2; j4++) {
        float p4A = preA * pm4A[j4];
        float p4B = preB * pm4B[j4];
#pragma unroll 1
        for (int j5 = 0; j5 < 4; j5++) {
            float p5A = p4A * pm5A[j5];
            float p5B = p4B * pm5B[j5];
            int pb = w * 64 + j4 * 32 + j5 * 8;     // pair base (8 pairs here)
            const ulonglong2* wp = reinterpret_cast<const ulonglong2*>(&smpair[pb * 8]);
            const ulonglong2* bq = reinterpret_cast<const ulonglong2*>(&smb[pb]);
#pragma unroll
            for (int j6 = 0; j6 < 4; j6++) {
                ull p6A = pack2(p5A * pm6A[j6]);
                ull p6B = pack2(p5B * pm6B[j6]);
                ull fA0 = mul2(p6A, pm7pA[0]);
                ull fA1 = mul2(p6A, pm7pA[1]);
                ull fB0 = mul2(p6B, pm7pB[0]);
                ull fB1 = mul2(p6B, pm7pB[1]);
                const ulonglong2* w0 = wp + j6 * 8;
                ulonglong2 q0 = w0[0], q1 = w0[1], q2 = w0[2], q3 = w0[3];
                ulonglong2 q4 = w0[4], q5 = w0[5], q6 = w0[6], q7 = w0[7];
                ulonglong2 bb = bq[j6];
                // pair 2*j6 (rules j7=0,1)
                fma2(aA[0], fA0, q0.x); fma2(aA[1], fA0, q0.y);
                fma2(aA[2], fA0, q1.x); fma2(aA[3], fA0, q1.y);
                fma2(aA[4], fA0, q2.x); fma2(aA[5], fA0, q2.y);
                fma2(aA[6], fA0, q3.x); fma2(aA[7], fA0, q3.y);
                fma2(aA[8], fA0, bb.x);
                fma2(aB[0], fB0, q0.x); fma2(aB[1], fB0, q0.y);
                fma2(aB[2], fB0, q1.x); fma2(aB[3], fB0, q1.y);
                fma2(aB[4], fB0, q2.x); fma2(aB[5], fB0, q2.y);
                fma2(aB[6], fB0, q3.x); fma2(aB[7], fB0, q3.y);
                fma2(aB[8], fB0, bb.x);
                // pair 2*j6+1 (rules j7=2,3)
                fma2(aA[0], fA1, q4.x); fma2(aA[1], fA1, q4.y);
                fma2(aA[2], fA1, q5.x); fma2(aA[3], fA1, q5.y);
                fma2(aA[4], fA1, q6.x); fma2(aA[5], fA1, q6.y);
                fma2(aA[6], fA1, q7.x); fma2(aA[7], fA1, q7.y);
                fma2(aA[8], fA1, bb.y);
                fma2(aB[0], fB1, q4.x); fma2(aB[1], fB1, q4.y);
                fma2(aB[2], fB1, q5.x); fma2(aB[3], fB1, q5.y);
                fma2(aB[4], fB1, q6.x); fma2(aB[5], fB1, q6.y);
                fma2(aB[6], fB1, q7.x); fma2(aB[7], fB1, q7.y);
                fma2(aB[8], fB1, bb.y);
            }
        }
    }

    // ---- collapse rule-pair lanes, cross-warp reduction ----
#pragma unroll
    for (int k = 0; k < 9; k++) {
        float lo, hi;
        unpack2(aA[k], lo, hi);
        red[w][lane][k] = lo + hi;
        unpack2(aB[k], lo, hi);
        red[w][lane + 32][k] = lo + hi;
    }
    __syncthreads();

#pragma unroll 1
    for (int idx = tid; idx < 9 * 64; idx += 128) {
        int s = idx & 63;
        int k = idx >> 6;
        float a = red[0][s][k] + red[1][s][k] + red[2][s][k] + red[3][s][k];
        g_part[(gy * 9 + k) * NSAMP + tile * 64 + s] = a;
    }

    // ---- fused finalize: last CTA of this tile reduces over all groups ----
    __threadfence();
    __syncthreads();
    if (tid == 0) {
        int c = atomicAdd(&g_cnt[tile], 1);
        isLast = (c == NGROUP - 1) ? 1 : 0;
    }
    __syncthreads();
    if (isLast) {
        __threadfence();
        float* sA = s_mg;  // reuse: [s][k] 64*9
#pragma unroll 1
        for (int item = tid; item < 9 * 64; item += 128) {
            int k = item >> 6, s = item & 63;
            const float* p = g_part + k * NSAMP + tile * 64 + s;
            float a0 = 0.f, a1 = 0.f, a2 = 0.f, a3 = 0.f;
#pragma unroll 4
            for (int g = 0; g < NGROUP; g += 4) {
                a0 += p[(g + 0) * 9 * NSAMP];
                a1 += p[(g + 1) * 9 * NSAMP];
                a2 += p[(g + 2) * 9 * NSAMP];
                a3 += p[(g + 3) * 9 * NSAMP];
            }
            sA[s * 9 + k] = (a0 + a1) + (a2 + a3);
        }
        __syncthreads();
        if (tid < 64) {
            int n = tile * 64 + tid;
            float o = sA[tid * 9 + 8];
#pragma unroll
            for (int m = 0; m < 8; m++) o = fmaf(x[n * 8 + m], sA[tid * 9 + m], o);
            out[n] = o;
        }
        if (tid == 0) g_cnt[tile] = 0;  // reset for next graph replay
    }
}

extern "C" void kernel_launch(void* const* d_in, const int* in_sizes, int n_in,
                              void* d_out, int out_size) {
    const float* x      = (const float*)d_in[0];
    const float* center = (const float*)d_in[1];
    const float* sigma  = (const float*)d_in[2];
    const float* W      = (const float*)d_in[3];
    const float* b      = (const float*)d_in[4];
    float* out = (float*)d_out;

    dim3 grid(TILES, NGROUP);
    tsk_kernel<<<grid, 128>>>(x, center, sigma, W, b, out);
}